// round 13
// baseline (speedup 1.0000x reference)
#include <cuda_runtime.h>
#include <cstdint>

#define BM 128
#define BN 128
#define BK 32
#define NTHREADS 128
#define STAGE_WORDS (BM * BK)                 // 4096 words = 16 KB per operand
#define SMEM_BYTES (2 * 2 * STAGE_WORDS * 4)  // 64 KB dynamic

// ---------------- scratch (device globals; no allocations allowed) ----------
__device__ float g_x[33554432];
__device__ float g_z[33554432];
__device__ float g_q[33554432];
__device__ float g_k[33554432];
__device__ float g_v[33554432];
__device__ float g_a[33554432];
__device__ float g_w[4194304];   // 4 pre-rounded weight matrices

// ---------------- helpers ----------------------------------------------------
__device__ __forceinline__ uint32_t cvt_tf32(float x) {
    uint32_t r;
    asm("cvt.rna.tf32.f32 %0, %1;" : "=r"(r) : "f"(x));
    return r;
}
__device__ __forceinline__ float round_tf32(float x) {
    return __uint_as_float(cvt_tf32(x));
}
__device__ __forceinline__ void cp_async16(uint32_t dst, const void* src) {
    asm volatile("cp.async.cg.shared.global [%0], [%1], 16;" :: "r"(dst), "l"(src));
}
__device__ __forceinline__ void cp_commit() {
    asm volatile("cp.async.commit_group;");
}

// NT (K-major) tile: row r x 32 k-words, 8 chunks of 4 words.
// phys chunk = (k>>2) ^ (r&7). Row stride 32 words == 0 mod 32 banks, so
// fragment-load bank = ((chunk^(r&7))*4 + (k&3)) -> all 32 banks distinct.
__device__ __forceinline__ int idxA(int r, int k) {
    return r * BK + ((((k >> 2) ^ (r & 7)) << 2) | (k & 3));
}
// NN B tile stored [k][128] (k=0..31) with quad ^= k&3 (proven R4-R12)
__device__ __forceinline__ int idxBnn(int k, int n) {
    return k * BN + ((((n >> 2) ^ (k & 3)) << 2) | (n & 3));
}

// ---------------- tf32 pre-rounding pass -------------------------------------
__global__ void round_kernel(const float* __restrict__ src, float* __restrict__ dst)
{
    int idx = blockIdx.x * blockDim.x + threadIdx.x;
    float4 v = reinterpret_cast<const float4*>(src)[idx];
    v.x = round_tf32(v.x); v.y = round_tf32(v.y);
    v.z = round_tf32(v.z); v.w = round_tf32(v.w);
    reinterpret_cast<float4*>(dst)[idx] = v;
}

// ---------------- gather: x = tf32(item_emb[positives] + pos_emb) ------------
__global__ void gather_kernel(const int* __restrict__ positives,
                              const float* __restrict__ item_emb,
                              const float* __restrict__ pos_emb,
                              float* __restrict__ x)
{
    int idx = blockIdx.x * blockDim.x + threadIdx.x;
    int row = idx >> 8;
    int c4  = idx & 255;
    int l   = row & 1023;
    int item = positives[row];
    float4 a = reinterpret_cast<const float4*>(item_emb)[(long long)item * 256 + c4];
    float4 p = reinterpret_cast<const float4*>(pos_emb)[l * 256 + c4];
    float4 o = make_float4(round_tf32(a.x + p.x), round_tf32(a.y + p.y),
                           round_tf32(a.z + p.z), round_tf32(a.w + p.w));
    reinterpret_cast<float4*>(x)[idx] = o;
}

// ---------------- tf32 tensor-core GEMM (128x128 block, 4 warps of 64x64) ----
// C[m,n] = sum_k A[m,k] * B(.,.)  where:
//   BNN=false: B is [N][K] row-major (NT, C = A @ B^T)
//   BNN=true : B is [K][N] row-major (NN, C = A @ B); enables causal k-trunc.
// EPI: 0 none, 1 silu->tf32, 2 col-scale->tf32, 3 attention score->tf32
//      (EPI==3 skips blocks fully above the diagonal: exact zeros)
template<int EPI, bool BNN>
__global__ void __launch_bounds__(NTHREADS, 2)
gemm_kernel(const float* __restrict__ Ag, const float* __restrict__ Bg,
            float* __restrict__ Cg, int M, int N, int K,
            long long sA, long long sB, long long sC,
            const float* __restrict__ gamma, const float* __restrict__ beta,
            const float* __restrict__ sw, const int* __restrict__ maskv,
            float scale)
{
    extern __shared__ uint32_t smem[];
    uint32_t* As = smem;                       // 2 x 4096 words
    uint32_t* Bs = smem + 2 * STAGE_WORDS;     // 2 x 4096 words

    const int b = blockIdx.z;
    Ag += (long long)b * sA;
    Bg += (long long)b * sB;
    Cg += (long long)b * sC;
    const int* mv = (EPI == 3) ? (maskv + (long long)b * N) : maskv;

    const int tid  = threadIdx.x;
    const int lane = tid & 31;
    const int warp = tid >> 5;
    const int wm = (warp >> 1) * 64;   // 2 warps along M
    const int wn = (warp & 1) * 64;    // 2 warps along N (64 cols each)
    const int m0 = blockIdx.y * BM;
    const int n0 = blockIdx.x * BN;
    const int tg = lane & 3;

    // Causal skip: score blocks strictly above the diagonal are entirely zero.
    if (EPI == 3 && n0 > m0 + BM - 1) {
        const float4 z4 = make_float4(0.f, 0.f, 0.f, 0.f);
        #pragma unroll
        for (int i = 0; i < (BM * BN / 4) / NTHREADS; i++) {
            int c = tid + i * NTHREADS;
            int r = c >> 5;          // 32 float4 per row
            int qd = c & 31;
            *reinterpret_cast<float4*>(&Cg[(long long)(m0 + r) * N + n0 + qd * 4]) = z4;
        }
        return;
    }

    float acc[4][8][4];
    #pragma unroll
    for (int i = 0; i < 4; i++)
        #pragma unroll
        for (int j = 0; j < 8; j++)
            #pragma unroll
            for (int c = 0; c < 4; c++) acc[i][j][c] = 0.f;

    int nK = K / BK;                   // 32
    if (BNN) {                         // A[m,k]=0 for k>m -> truncate k-loop
        int lim = (m0 + BM) / BK;
        if (lim < nK) nK = lim;
    }

    auto loadStage = [&](int ks, int buf) {
        const int k0 = ks * BK;
        uint32_t abase = (uint32_t)__cvta_generic_to_shared(&As[buf * STAGE_WORDS]);
        uint32_t bbase = (uint32_t)__cvta_generic_to_shared(&Bs[buf * STAGE_WORDS]);
        // A tile: 128 rows x 8 chunks = 1024 cp.async (8 per thread)
        #pragma unroll
        for (int i = 0; i < 8; i++) {
            int c = tid + i * NTHREADS;
            int r = c >> 3, q = c & 7;
            const float* src = Ag + (long long)(m0 + r) * K + k0 + q * 4;
            cp_async16(abase + (r * BK + ((q ^ (r & 7)) << 2)) * 4, src);
        }
        if (BNN) {
            // B tile: 32 rows(k) x 32 chunks = 1024 cp.async
            #pragma unroll
            for (int i = 0; i < 8; i++) {
                int c = tid + i * NTHREADS;
                int k = c >> 5, nq = c & 31;
                const float* src = Bg + (long long)(k0 + k) * N + n0 + nq * 4;
                int pq = nq ^ (k & 3);
                cp_async16(bbase + (k * BN + pq * 4) * 4, src);
            }
        } else {
            // B tile: 128 rows(n) x 8 chunks = 1024 cp.async
            #pragma unroll
            for (int i = 0; i < 8; i++) {
                int c = tid + i * NTHREADS;
                int r = c >> 3, q = c & 7;
                const float* src = Bg + (long long)(n0 + r) * K + k0 + q * 4;
                cp_async16(bbase + (r * BK + ((q ^ (r & 7)) << 2)) * 4, src);
            }
        }
        cp_commit();
    };

    loadStage(0, 0);

    for (int ks = 0; ks < nK; ks++) {
        if (ks + 1 < nK) {
            loadStage(ks + 1, (ks + 1) & 1);
            asm volatile("cp.async.wait_group 1;");
        } else {
            asm volatile("cp.async.wait_group 0;");
        }
        __syncthreads();

        const uint32_t* as = &As[(ks & 1) * STAGE_WORDS];
        const uint32_t* bs = &Bs[(ks & 1) * STAGE_WORDS];

        #pragma unroll
        for (int kk = 0; kk < BK; kk += 8) {
            const int kc = kk + tg;
            uint32_t af[4][4];
            #pragma unroll
            for (int mt = 0; mt < 4; mt++) {
                int r = wm + mt * 16 + (lane >> 2);
                af[mt][0] = as[idxA(r,     kc)];
                af[mt][1] = as[idxA(r + 8, kc)];
                af[mt][2] = as[idxA(r,     kc + 4)];
                af[mt][3] = as[idxA(r + 8, kc + 4)];
            }
            uint32_t bf[8][2];
            #pragma unroll
            for (int nt = 0; nt < 8; nt++) {
                int n = wn + nt * 8 + (lane >> 2);
                if (BNN) {
                    bf[nt][0] = bs[idxBnn(kc,     n)];
                    bf[nt][1] = bs[idxBnn(kc + 4, n)];
                } else {
                    bf[nt][0] = bs[idxA(n, kc)];
                    bf[nt][1] = bs[idxA(n, kc + 4)];
                }
            }
            #pragma unroll
            for (int mt = 0; mt < 4; mt++)
                #pragma unroll
                for (int nt = 0; nt < 8; nt++) {
                    asm volatile(
                        "mma.sync.aligned.m16n8k8.row.col.f32.tf32.tf32.f32 "
                        "{%0,%1,%2,%3}, {%4,%5,%6,%7}, {%8,%9}, {%0,%1,%2,%3};"
                        : "+f"(acc[mt][nt][0]), "+f"(acc[mt][nt][1]),
                          "+f"(acc[mt][nt][2]), "+f"(acc[mt][nt][3])
                        : "r"(af[mt][0]), "r"(af[mt][1]), "r"(af[mt][2]), "r"(af[mt][3]),
                          "r"(bf[nt][0]), "r"(bf[nt][1]));
                }
        }
        __syncthreads();
    }

    // ---------------- epilogue ----------------
    #pragma unroll
    for (int mt = 0; mt < 4; mt++) {
        #pragma unroll
        for (int half = 0; half < 2; half++) {
            const int m = m0 + wm + mt * 16 + (lane >> 2) + half * 8;
            #pragma unroll
            for (int nt = 0; nt < 8; nt++) {
                const int n = n0 + wn + nt * 8 + tg * 2;
                float v0 = acc[mt][nt][half * 2 + 0];
                float v1 = acc[mt][nt][half * 2 + 1];
                if (EPI == 1) {                 // silu, rounded for next GEMM
                    v0 = round_tf32(v0 / (1.f + __expf(-v0)));
                    v1 = round_tf32(v1 / (1.f + __expf(-v1)));
                } else if (EPI == 2) {          // per-column scale+shift, rounded
                    v0 = round_tf32(v0 * gamma[n]     + beta[n]);
                    v1 = round_tf32(v1 * gamma[n + 1] + beta[n + 1]);
                } else if (EPI == 3) {          // attention score, rounded
                    bool keep0 = (m == n)     || (mv[n]     && n     <= m);
                    bool keep1 = (m == n + 1) || (mv[n + 1] && n + 1 <= m);
                    float s0 = keep0 ? v0 * sw[(long long)m * N + n]     : 0.f;
                    float s1 = keep1 ? v1 * sw[(long long)m * N + n + 1] : 0.f;
                    s0 = fmaxf(s0, 0.f);
                    s1 = fmaxf(s1, 0.f);
                    v0 = round_tf32(s0 * s0 * scale);
                    v1 = round_tf32(s1 * s1 * scale);
                }
                *reinterpret_cast<float2*>(&Cg[(long long)m * N + n]) = make_float2(v0, v1);
            }
        }
    }
}

// ---------------- launch ------------------------------------------------------
extern "C" void kernel_launch(void* const* d_in, const int* in_sizes, int n_in,
                              void* d_out, int out_size)
{
    const int*   positives = (const int*)  d_in[0];
    const int*   mask      = (const int*)  d_in[1];
    const float* item_emb  = (const float*)d_in[2];
    const float* pos_emb   = (const float*)d_in[3];
    const float* Wz        = (const float*)d_in[4];
    const float* Wv        = (const float*)d_in[5];
    const float* Wq        = (const float*)d_in[6];
    const float* Wk        = (const float*)d_in[7];
    const float* gq        = (const float*)d_in[8];
    const float* bq        = (const float*)d_in[9];
    const float* gk        = (const float*)d_in[10];
    const float* bk        = (const float*)d_in[11];
    const float* sw        = (const float*)d_in[12];
    float* out = (float*)d_out;

    float *x, *z, *q, *k, *v, *a, *w;
    cudaGetSymbolAddress((void**)&x, g_x);
    cudaGetSymbolAddress((void**)&z, g_z);
    cudaGetSymbolAddress((void**)&q, g_q);
    cudaGetSymbolAddress((void**)&k, g_k);
    cudaGetSymbolAddress((void**)&v, g_v);
    cudaGetSymbolAddress((void**)&a, g_a);
    cudaGetSymbolAddress((void**)&w, g_w);

    cudaFuncSetAttribute(gemm_kernel<0, true>,  cudaFuncAttributeMaxDynamicSharedMemorySize, SMEM_BYTES);
    cudaFuncSetAttribute(gemm_kernel<1, false>, cudaFuncAttributeMaxDynamicSharedMemorySize, SMEM_BYTES);
    cudaFuncSetAttribute(gemm_kernel<2, false>, cudaFuncAttributeMaxDynamicSharedMemorySize, SMEM_BYTES);
    cudaFuncSetAttribute(gemm_kernel<3, false>, cudaFuncAttributeMaxDynamicSharedMemorySize, SMEM_BYTES);

    const int M = 32768, L = 1024;
    const long long SL = (long long)L * L;
    float* wz = w;
    float* wv = w + 1048576;
    float* wq = w + 2097152;
    float* wk = w + 3145728;

    round_kernel<<<1024, 256>>>(Wz, wz);
    round_kernel<<<1024, 256>>>(Wv, wv);
    round_kernel<<<1024, 256>>>(Wq, wq);
    round_kernel<<<1024, 256>>>(Wk, wk);

    gather_kernel<<<32768, 256>>>(positives, item_emb, pos_emb, x);

    dim3 gBig(L / BN, M / BM, 1);
    // z = tf32(silu(x @ Wz^T))
    gemm_kernel<1, false><<<gBig, NTHREADS, SMEM_BYTES>>>(x, wz, z, M, L, L, 0, 0, 0,
                                              nullptr, nullptr, nullptr, nullptr, 0.f);
    // v = tf32(silu(x @ Wv^T))
    gemm_kernel<1, false><<<gBig, NTHREADS, SMEM_BYTES>>>(x, wv, v, M, L, L, 0, 0, 0,
                                              nullptr, nullptr, nullptr, nullptr, 0.f);
    // q = tf32((z @ Wq^T)*gamma_q+beta_q)
    gemm_kernel<2, false><<<gBig, NTHREADS, SMEM_BYTES>>>(z, wq, q, M, L, L, 0, 0, 0,
                                              gq, bq, nullptr, nullptr, 0.f);
    // k = tf32((z @ Wk^T)*gamma_k+beta_k)
    gemm_kernel<2, false><<<gBig, NTHREADS, SMEM_BYTES>>>(z, wk, k, M, L, L, 0, 0, 0,
                                              gk, bk, nullptr, nullptr, 0.f);

    dim3 gAtt(L / BN, L / BM, 32);
    // a = tf32(relu((q @ k^T)*keep*sparse_w)^2 / (L*D)); upper blocks skipped
    gemm_kernel<3, false><<<gAtt, NTHREADS, SMEM_BYTES>>>(q, k, a, L, L, L, SL, SL, SL,
                                              nullptr, nullptr, sw, mask,
                                              1.f / 1048576.f);
    // out = a @ v; causal k-truncation per block row
    gemm_kernel<0, true><<<gAtt, NTHREADS, SMEM_BYTES>>>(a, v, out, L, L, L, SL, SL, SL,
                                             nullptr, nullptr, nullptr, nullptr, 0.f);
}

// round 14
// speedup vs baseline: 1.7386x; 1.7386x over previous
#include <cuda_runtime.h>
#include <cstdint>

#define BM 128
#define BN 128
#define BK 16
#define NTHREADS 128
#define STAGES 3

// ---------------- scratch (device globals; no allocations allowed) ----------
__device__ float g_x[33554432];
__device__ float g_z[33554432];
__device__ float g_q[33554432];
__device__ float g_k[33554432];
__device__ float g_v[33554432];
__device__ float g_a[33554432];
__device__ float g_w[4194304];   // 4 pre-rounded weight matrices

// ---------------- helpers ----------------------------------------------------
__device__ __forceinline__ uint32_t cvt_tf32(float x) {
    uint32_t r;
    asm("cvt.rna.tf32.f32 %0, %1;" : "=r"(r) : "f"(x));
    return r;
}
__device__ __forceinline__ float round_tf32(float x) {
    return __uint_as_float(cvt_tf32(x));
}
__device__ __forceinline__ void cp_async16(uint32_t dst, const void* src) {
    asm volatile("cp.async.cg.shared.global [%0], [%1], 16;" :: "r"(dst), "l"(src));
}
__device__ __forceinline__ void cp_commit() {
    asm volatile("cp.async.commit_group;");
}

// swizzled smem index for K-major (NT) tiles: row r x 16 k-words,
// phys quad = (k>>2) ^ ((r>>1)&3). Proven conflict-free in R2-R12 runs.
__device__ __forceinline__ int idxA(int r, int k) {
    return r * BK + ((((k >> 2) ^ ((r >> 1) & 3)) << 2) | (k & 3));
}
// NN B tile stored [k][128] with quad ^= k&3
__device__ __forceinline__ int idxBnn(int k, int n) {
    return k * BN + ((((n >> 2) ^ (k & 3)) << 2) | (n & 3));
}

// ---------------- tf32 pre-rounding pass (all 4 weight matrices) -------------
__global__ void round_kernel(const float* __restrict__ s0, const float* __restrict__ s1,
                             const float* __restrict__ s2, const float* __restrict__ s3,
                             float* __restrict__ dst)
{
    int idx = blockIdx.x * blockDim.x + threadIdx.x;   // 0 .. 4*262144-1
    int wsel = idx >> 18;                               // 262144 float4 per matrix
    int off  = idx & 262143;
    const float* src = (wsel == 0) ? s0 : (wsel == 1) ? s1 : (wsel == 2) ? s2 : s3;
    float4 v = reinterpret_cast<const float4*>(src)[off];
    v.x = round_tf32(v.x); v.y = round_tf32(v.y);
    v.z = round_tf32(v.z); v.w = round_tf32(v.w);
    reinterpret_cast<float4*>(dst)[idx] = v;
}

// ---------------- gather: x = tf32(item_emb[positives] + pos_emb) ------------
__global__ void gather_kernel(const int* __restrict__ positives,
                              const float* __restrict__ item_emb,
                              const float* __restrict__ pos_emb,
                              float* __restrict__ x)
{
    int idx = blockIdx.x * blockDim.x + threadIdx.x;
    int row = idx >> 8;
    int c4  = idx & 255;
    int l   = row & 1023;
    int item = positives[row];
    float4 a = reinterpret_cast<const float4*>(item_emb)[(long long)item * 256 + c4];
    float4 p = reinterpret_cast<const float4*>(pos_emb)[l * 256 + c4];
    float4 o = make_float4(round_tf32(a.x + p.x), round_tf32(a.y + p.y),
                           round_tf32(a.z + p.z), round_tf32(a.w + p.w));
    reinterpret_cast<float4*>(x)[idx] = o;
}

// ---------------- tf32 tensor-core GEMM (block 128x128, 4 warps of 64x64) ----
// C[m,n] = sum_k A[m,k] * B(.,.)  where:
//   BNN=false: B is [N][K] row-major (NT, C = A @ B^T)
//   BNN=true : B is [K][N] row-major (NN, C = A @ B); enables causal k-trunc.
// EPI: 0 none, 1 silu->tf32, 2 col-scale->tf32, 3 attention score->tf32
//      (EPI==3 skips blocks fully above the diagonal: exact zeros)
template<int EPI, bool BNN>
__global__ void __launch_bounds__(NTHREADS, 2)
gemm_kernel(const float* __restrict__ Ag, const float* __restrict__ Bg,
            float* __restrict__ Cg, int M, int N, int K,
            long long sA, long long sB, long long sC,
            const float* __restrict__ gamma, const float* __restrict__ beta,
            const float* __restrict__ sw, const int* __restrict__ maskv,
            float scale)
{
    __shared__ uint32_t As[STAGES][BM * BK];   // 3 x 8 KB
    __shared__ uint32_t Bs[STAGES][BN * BK];   // 3 x 8 KB   (48 KB total)

    const int b = blockIdx.z;
    Ag += (long long)b * sA;
    Bg += (long long)b * sB;
    Cg += (long long)b * sC;
    const int* mv = (EPI == 3) ? (maskv + (long long)b * N) : maskv;

    const int tid  = threadIdx.x;
    const int lane = tid & 31;
    const int warp = tid >> 5;
    const int wm = (warp >> 1) * 64;   // 2 warps along M
    const int wn = (warp & 1) * 64;    // 2 warps along N (64 cols each)
    const int m0 = blockIdx.y * BM;
    const int n0 = blockIdx.x * BN;
    const int tg = lane & 3;

    // Causal skip: score blocks strictly above the diagonal are entirely zero.
    if (EPI == 3 && n0 > m0 + BM - 1) {
        const float4 z4 = make_float4(0.f, 0.f, 0.f, 0.f);
        #pragma unroll
        for (int i = 0; i < (BM * BN / 4) / NTHREADS; i++) {
            int c = tid + i * NTHREADS;
            int r = c >> 5;          // 32 float4 per row
            int qd = c & 31;
            *reinterpret_cast<float4*>(&Cg[(long long)(m0 + r) * N + n0 + qd * 4]) = z4;
        }
        return;
    }

    float acc[4][8][4];
    #pragma unroll
    for (int i = 0; i < 4; i++)
        #pragma unroll
        for (int j = 0; j < 8; j++)
            #pragma unroll
            for (int c = 0; c < 4; c++) acc[i][j][c] = 0.f;

    int nK = K / BK;
    if (BNN) {                         // A[m,k]=0 for k>m -> truncate k-loop
        int lim = (m0 + BM) / BK;
        if (lim < nK) nK = lim;
    }

    auto loadStage = [&](int ks, int buf) {
        const int k0 = ks * BK;
        // A tile: 128 rows x 4 chunks = 512 cp.async (4 per thread)
        #pragma unroll
        for (int i = 0; i < 4; i++) {
            int c = tid + i * NTHREADS;
            int r = c >> 2, q = c & 3;
            const float* src = Ag + (long long)(m0 + r) * K + k0 + q * 4;
            int pq = q ^ ((r >> 1) & 3);
            cp_async16(__cvta_generic_to_shared(&As[buf][r * BK + pq * 4]), src);
        }
        if (BNN) {
            // B tile: 16 rows(k) x 32 chunks = 512 cp.async
            #pragma unroll
            for (int i = 0; i < 4; i++) {
                int c = tid + i * NTHREADS;
                int k = c >> 5, nq = c & 31;
                const float* src = Bg + (long long)(k0 + k) * N + n0 + nq * 4;
                int pq = nq ^ (k & 3);
                cp_async16(__cvta_generic_to_shared(&Bs[buf][k * BN + pq * 4]), src);
            }
        } else {
            // B tile: 128 rows(n) x 4 chunks = 512 cp.async
            #pragma unroll
            for (int i = 0; i < 4; i++) {
                int c = tid + i * NTHREADS;
                int r = c >> 2, q = c & 3;
                const float* src = Bg + (long long)(n0 + r) * K + k0 + q * 4;
                int pq = q ^ ((r >> 1) & 3);
                cp_async16(__cvta_generic_to_shared(&Bs[buf][r * BK + pq * 4]), src);
            }
        }
        cp_commit();
    };

    // prime STAGES-1 = 2 stages ahead
    loadStage(0, 0);
    if (nK > 1) loadStage(1, 1);

    int buf = 0;
    for (int ks = 0; ks < nK; ks++) {
        if (ks + 2 < nK) {
            loadStage(ks + 2, (ks + 2) % STAGES);
            asm volatile("cp.async.wait_group 2;");
        } else if (ks + 1 < nK) {
            asm volatile("cp.async.wait_group 1;");
        } else {
            asm volatile("cp.async.wait_group 0;");
        }
        __syncthreads();

        const uint32_t* as = As[buf];
        const uint32_t* bs = Bs[buf];
        buf = (buf + 1 == STAGES) ? 0 : buf + 1;

        #pragma unroll
        for (int kk = 0; kk < BK; kk += 8) {
            const int kc = kk + tg;
            uint32_t af[4][4];
            #pragma unroll
            for (int mt = 0; mt < 4; mt++) {
                int r = wm + mt * 16 + (lane >> 2);
                af[mt][0] = as[idxA(r,     kc)];
                af[mt][1] = as[idxA(r + 8, kc)];
                af[mt][2] = as[idxA(r,     kc + 4)];
                af[mt][3] = as[idxA(r + 8, kc + 4)];
            }
            uint32_t bf[8][2];
            #pragma unroll
            for (int nt = 0; nt < 8; nt++) {
                int n = wn + nt * 8 + (lane >> 2);
                if (BNN) {
                    bf[nt][0] = bs[idxBnn(kc,     n)];
                    bf[nt][1] = bs[idxBnn(kc + 4, n)];
                } else {
                    bf[nt][0] = bs[idxA(n, kc)];
                    bf[nt][1] = bs[idxA(n, kc + 4)];
                }
            }
            #pragma unroll
            for (int mt = 0; mt < 4; mt++)
                #pragma unroll
                for (int nt = 0; nt < 8; nt++) {
                    asm volatile(
                        "mma.sync.aligned.m16n8k8.row.col.f32.tf32.tf32.f32 "
                        "{%0,%1,%2,%3}, {%4,%5,%6,%7}, {%8,%9}, {%0,%1,%2,%3};"
                        : "+f"(acc[mt][nt][0]), "+f"(acc[mt][nt][1]),
                          "+f"(acc[mt][nt][2]), "+f"(acc[mt][nt][3])
                        : "r"(af[mt][0]), "r"(af[mt][1]), "r"(af[mt][2]), "r"(af[mt][3]),
                          "r"(bf[nt][0]), "r"(bf[nt][1]));
                }
        }
        __syncthreads();
    }

    // ---------------- epilogue ----------------
    #pragma unroll
    for (int mt = 0; mt < 4; mt++) {
        #pragma unroll
        for (int half = 0; half < 2; half++) {
            const int m = m0 + wm + mt * 16 + (lane >> 2) + half * 8;
            #pragma unroll
            for (int nt = 0; nt < 8; nt++) {
                const int n = n0 + wn + nt * 8 + tg * 2;
                float v0 = acc[mt][nt][half * 2 + 0];
                float v1 = acc[mt][nt][half * 2 + 1];
                if (EPI == 1) {                 // silu, rounded for next GEMM
                    v0 = round_tf32(v0 / (1.f + __expf(-v0)));
                    v1 = round_tf32(v1 / (1.f + __expf(-v1)));
                } else if (EPI == 2) {          // per-column scale+shift, rounded
                    v0 = round_tf32(v0 * gamma[n]     + beta[n]);
                    v1 = round_tf32(v1 * gamma[n + 1] + beta[n + 1]);
                } else if (EPI == 3) {          // attention score, rounded
                    bool keep0 = (m == n)     || (mv[n]     && n     <= m);
                    bool keep1 = (m == n + 1) || (mv[n + 1] && n + 1 <= m);
                    float s0 = keep0 ? v0 * sw[(long long)m * N + n]     : 0.f;
                    float s1 = keep1 ? v1 * sw[(long long)m * N + n + 1] : 0.f;
                    s0 = fmaxf(s0, 0.f);
                    s1 = fmaxf(s1, 0.f);
                    v0 = round_tf32(s0 * s0 * scale);
                    v1 = round_tf32(s1 * s1 * scale);
                }
                *reinterpret_cast<float2*>(&Cg[(long long)m * N + n]) = make_float2(v0, v1);
            }
        }
    }
}

// ---------------- launch ------------------------------------------------------
extern "C" void kernel_launch(void* const* d_in, const int* in_sizes, int n_in,
                              void* d_out, int out_size)
{
    const int*   positives = (const int*)  d_in[0];
    const int*   mask      = (const int*)  d_in[1];
    const float* item_emb  = (const float*)d_in[2];
    const float* pos_emb   = (const float*)d_in[3];
    const float* Wz        = (const float*)d_in[4];
    const float* Wv        = (const float*)d_in[5];
    const float* Wq        = (const float*)d_in[6];
    const float* Wk        = (const float*)d_in[7];
    const float* gq        = (const float*)d_in[8];
    const float* bq        = (const float*)d_in[9];
    const float* gk        = (const float*)d_in[10];
    const float* bk        = (const float*)d_in[11];
    const float* sw        = (const float*)d_in[12];
    float* out = (float*)d_out;

    float *x, *z, *q, *k, *v, *a, *w;
    cudaGetSymbolAddress((void**)&x, g_x);
    cudaGetSymbolAddress((void**)&z, g_z);
    cudaGetSymbolAddress((void**)&q, g_q);
    cudaGetSymbolAddress((void**)&k, g_k);
    cudaGetSymbolAddress((void**)&v, g_v);
    cudaGetSymbolAddress((void**)&a, g_a);
    cudaGetSymbolAddress((void**)&w, g_w);

    const int M = 32768, L = 1024;
    const long long SL = (long long)L * L;
    float* wz = w;
    float* wv = w + 1048576;
    float* wq = w + 2097152;
    float* wk = w + 3145728;

    // one launch rounds all 4 weight matrices (dst = g_w, laid out in order)
    round_kernel<<<4096, 256>>>(Wz, Wv, Wq, Wk, w);

    gather_kernel<<<32768, 256>>>(positives, item_emb, pos_emb, x);

    dim3 gBig(L / BN, M / BM, 1);
    // z = tf32(silu(x @ Wz^T))
    gemm_kernel<1, false><<<gBig, NTHREADS>>>(x, wz, z, M, L, L, 0, 0, 0,
                                              nullptr, nullptr, nullptr, nullptr, 0.f);
    // v = tf32(silu(x @ Wv^T))
    gemm_kernel<1, false><<<gBig, NTHREADS>>>(x, wv, v, M, L, L, 0, 0, 0,
                                              nullptr, nullptr, nullptr, nullptr, 0.f);
    // q = tf32((z @ Wq^T)*gamma_q+beta_q)
    gemm_kernel<2, false><<<gBig, NTHREADS>>>(z, wq, q, M, L, L, 0, 0, 0,
                                              gq, bq, nullptr, nullptr, 0.f);
    // k = tf32((z @ Wk^T)*gamma_k+beta_k)
    gemm_kernel<2, false><<<gBig, NTHREADS>>>(z, wk, k, M, L, L, 0, 0, 0,
                                              gk, bk, nullptr, nullptr, 0.f);

    dim3 gAtt(L / BN, L / BM, 32);
    // a = tf32(relu((q @ k^T)*keep*sparse_w)^2 / (L*D)); upper blocks skipped
    gemm_kernel<3, false><<<gAtt, NTHREADS>>>(q, k, a, L, L, L, SL, SL, SL,
                                              nullptr, nullptr, sw, mask,
                                              1.f / 1048576.f);
    // out = a @ v; causal k-truncation per block row
    gemm_kernel<0, true><<<gAtt, NTHREADS>>>(a, v, out, L, L, L, SL, SL, SL,
                                             nullptr, nullptr, nullptr, nullptr, 0.f);
}